// round 1
// baseline (speedup 1.0000x reference)
#include <cuda_runtime.h>

#define H    32
#define FE   4
#define NMAX 100000
#define NL   3

// ---- scratch (no allocation allowed) ----
__device__ float4 d_T[NMAX * 8];     // T = node_in @ W_msg[:34]   [N][32] as float4[ N ][8]
__device__ float4 d_agg[NMAX * 8];   // scatter-sum accumulator    [N][32]
__device__ float  d_h[NMAX * H];     // hidden state
__device__ float  d_pool[H];         // column sums of h (for mean pooling)
__device__ float  d_g[H];            // global supernode state

// ---------------------------------------------------------------------------
// init: V[:,0]=1, V[:,1]=0 ; h = P_Q @ W_in + b_in ; g = 0
// one thread per (node, j)
// ---------------------------------------------------------------------------
__global__ void init_kernel(const float* __restrict__ PQ,
                            const float* __restrict__ Win,
                            const float* __restrict__ bin,
                            float* __restrict__ V, int N) {
    int gid = blockIdx.x * blockDim.x + threadIdx.x;
    if (gid < H) d_g[gid] = 0.f;
    if (gid < N * 2) V[gid] = (gid & 1) ? 0.f : 1.f;
    if (gid >= N * H) return;
    int i = gid >> 5, j = gid & 31;
    float p = __ldg(&PQ[i * 2]);
    float q = __ldg(&PQ[i * 2 + 1]);
    d_h[gid] = p * __ldg(&Win[j]) + q * __ldg(&Win[H + j]) + __ldg(&bin[j]);
}

// ---------------------------------------------------------------------------
// prep: T[i][j] = [V_i(2), h_i(32)] . W_msg[l][0:34][j] ; zero agg + pool
// one thread per (node, j); warp = one node
// ---------------------------------------------------------------------------
__global__ void prep_kernel(const float* __restrict__ V,
                            const float* __restrict__ Wmsg,  // layer base, 38*32
                            int N) {
    __shared__ float Ws[34 * H];
    __shared__ float hs[8][H];
    for (int t = threadIdx.x; t < 34 * H; t += blockDim.x)
        Ws[t] = Wmsg[t];
    __syncthreads();

    int gid = blockIdx.x * blockDim.x + threadIdx.x;
    if (gid < H) d_pool[gid] = 0.f;
    if (gid >= N * H) return;
    int i = gid >> 5, j = gid & 31;
    int w = threadIdx.x >> 5;

    hs[w][j] = d_h[i * H + j];
    __syncwarp();

    float v0 = __ldg(&V[i * 2]);
    float v1 = __ldg(&V[i * 2 + 1]);
    float acc = v0 * Ws[j] + v1 * Ws[H + j];
#pragma unroll
    for (int k = 0; k < H; k++)
        acc += hs[w][k] * Ws[(2 + k) * H + j];

    ((float*)d_T)[gid]   = acc;
    ((float*)d_agg)[gid] = 0.f;
}

// ---------------------------------------------------------------------------
// edge: m = (T[s] + EF @ W_ef + b) * mask ; red.v4 into agg[r]
// 8 threads per edge, each owns a float4 slice (j = tid % 8)
// ---------------------------------------------------------------------------
__global__ void edge_kernel(const int*   __restrict__ senders,
                            const int*   __restrict__ receivers,
                            const float* __restrict__ ef,
                            const float* __restrict__ mask,
                            const float* __restrict__ Wmsg,  // layer base, 38*32
                            const float* __restrict__ bmsg,  // layer base, 32
                            int E) {
    long gid = (long)blockIdx.x * blockDim.x + threadIdx.x;
    int  j = (int)(gid & 7);
    long e = gid >> 3;
    if (e >= E) return;

    // per-thread weight slice (broadcast loads, L1-resident)
    float4 w0 = *(const float4*)&Wmsg[34 * H + j * 4];
    float4 w1 = *(const float4*)&Wmsg[35 * H + j * 4];
    float4 w2 = *(const float4*)&Wmsg[36 * H + j * 4];
    float4 w3 = *(const float4*)&Wmsg[37 * H + j * 4];
    float4 b  = *(const float4*)&bmsg[j * 4];

    int   s  = __ldg(&senders[e]);
    int   r  = __ldg(&receivers[e]);
    float mk = __ldg(&mask[e]);
    float4 f = __ldg((const float4*)ef + e);
    float4 t = __ldg(&d_T[(long)s * 8 + j]);

    float4 m;
    m.x = (t.x + b.x + f.x * w0.x + f.y * w1.x + f.z * w2.x + f.w * w3.x) * mk;
    m.y = (t.y + b.y + f.x * w0.y + f.y * w1.y + f.z * w2.y + f.w * w3.y) * mk;
    m.z = (t.z + b.z + f.x * w0.z + f.y * w1.z + f.z * w2.z + f.w * w3.z) * mk;
    m.w = (t.w + b.w + f.x * w0.w + f.y * w1.w + f.z * w2.w + f.w * w3.w) * mk;

    float4* dst = &d_agg[(long)r * 8 + j];
    asm volatile("red.global.add.v4.f32 [%0], {%1,%2,%3,%4};"
                 :: "l"(dst), "f"(m.x), "f"(m.y), "f"(m.z), "f"(m.w)
                 : "memory");
}

// ---------------------------------------------------------------------------
// reduce: h = relu(agg) ; d_pool += column sums (for mean)
// grid-stride; stride is a multiple of 32 so each thread's column is fixed
// ---------------------------------------------------------------------------
__global__ void reduce_kernel(int N) {
    __shared__ float sm[256];
    int total = N * H;
    float lsum = 0.f;
    for (int idx = blockIdx.x * blockDim.x + threadIdx.x; idx < total;
         idx += gridDim.x * blockDim.x) {
        float v = ((const float*)d_agg)[idx];
        v = fmaxf(v, 0.f);
        d_h[idx] = v;
        lsum += v;
    }
    sm[threadIdx.x] = lsum;
    __syncthreads();
#pragma unroll
    for (int off = 128; off >= 32; off >>= 1) {
        if (threadIdx.x < off) sm[threadIdx.x] += sm[threadIdx.x + off];
        __syncthreads();
    }
    if (threadIdx.x < 32) atomicAdd(&d_pool[threadIdx.x], sm[threadIdx.x]);
}

// ---------------------------------------------------------------------------
// global node: g = relu([g, mean(h)] @ W_g + b_g)   (1 block, 32 threads)
// ---------------------------------------------------------------------------
__global__ void g_kernel(const float* __restrict__ Wg,
                         const float* __restrict__ bg, float invN) {
    __shared__ float gin[2 * H];
    int t = threadIdx.x;
    gin[t]     = d_g[t];
    gin[H + t] = d_pool[t] * invN;
    __syncthreads();
    float acc = bg[t];
#pragma unroll
    for (int k = 0; k < 2 * H; k++)
        acc += gin[k] * Wg[k * H + t];
    d_g[t] = fmaxf(acc, 0.f);
}

// ---------------------------------------------------------------------------
// node update: u = relu([h, g] @ W_n + b_n) ; V += u @ W_out + b_out ; h = u
// warp = one node, lane = output column
// ---------------------------------------------------------------------------
__global__ void node_kernel(const float* __restrict__ Wn,
                            const float* __restrict__ bn,
                            const float* __restrict__ Wout,
                            const float* __restrict__ bout,
                            float* __restrict__ V, int N) {
    __shared__ float Ws[2 * H * H];   // 8 KB
    __shared__ float gs[H];
    __shared__ float hs[8][H];
    for (int t = threadIdx.x; t < 2 * H * H; t += blockDim.x) Ws[t] = Wn[t];
    if (threadIdx.x < H) gs[threadIdx.x] = d_g[threadIdx.x];
    __syncthreads();

    int w = threadIdx.x >> 5, j = threadIdx.x & 31;
    int i = blockIdx.x * 8 + w;
    if (i >= N) return;

    hs[w][j] = d_h[i * H + j];
    __syncwarp();

    float acc = bn[j];
#pragma unroll
    for (int k = 0; k < H; k++) acc += hs[w][k] * Ws[k * H + j];
#pragma unroll
    for (int k = 0; k < H; k++) acc += gs[k] * Ws[(H + k) * H + j];
    float u = fmaxf(acc, 0.f);
    d_h[i * H + j] = u;

    float v0 = u * __ldg(&Wout[j * 2]);
    float v1 = u * __ldg(&Wout[j * 2 + 1]);
#pragma unroll
    for (int off = 16; off; off >>= 1) {
        v0 += __shfl_xor_sync(0xffffffffu, v0, off);
        v1 += __shfl_xor_sync(0xffffffffu, v1, off);
    }
    if (j == 0) {
        V[i * 2]     += v0 + __ldg(&bout[0]);
        V[i * 2 + 1] += v1 + __ldg(&bout[1]);
    }
}

// ---------------------------------------------------------------------------
extern "C" void kernel_launch(void* const* d_in, const int* in_sizes, int n_in,
                              void* d_out, int out_size) {
    const float* PQ        = (const float*)d_in[0];
    const int*   senders   = (const int*)  d_in[1];
    const int*   receivers = (const int*)  d_in[2];
    const float* ef        = (const float*)d_in[3];
    const float* mask      = (const float*)d_in[4];
    const float* Win       = (const float*)d_in[5];
    const float* bin       = (const float*)d_in[6];
    const float* Wmsg      = (const float*)d_in[7];
    const float* bmsg      = (const float*)d_in[8];
    const float* Wg        = (const float*)d_in[9];
    const float* bg        = (const float*)d_in[10];
    const float* Wn        = (const float*)d_in[11];
    const float* bn        = (const float*)d_in[12];
    const float* Wout      = (const float*)d_in[13];
    const float* bout      = (const float*)d_in[14];
    float* V = (float*)d_out;

    int N = in_sizes[0] / 2;
    int E = in_sizes[1];

    int nb_nh = (N * H + 255) / 256;
    init_kernel<<<nb_nh, 256>>>(PQ, Win, bin, V, N);

    for (int l = 0; l < NL; l++) {
        prep_kernel<<<nb_nh, 256>>>(V, Wmsg + l * 38 * H, N);

        long tot  = (long)E * 8;
        int  nb_e = (int)((tot + 255) / 256);
        edge_kernel<<<nb_e, 256>>>(senders, receivers, ef, mask,
                                   Wmsg + l * 38 * H, bmsg + l * H, E);

        reduce_kernel<<<2048, 256>>>(N);
        g_kernel<<<1, 32>>>(Wg + l * 2 * H * H, bg + l * H, 1.0f / (float)N);
        node_kernel<<<(N + 7) / 8, 256>>>(Wn + l * 2 * H * H, bn + l * H,
                                          Wout + l * H * 2, bout + l * 2, V, N);
    }
}